// round 1
// baseline (speedup 1.0000x reference)
#include <cuda_runtime.h>
#include <math.h>

#define BB 2
#define NN 320
#define DD 128
#define LL 4
#define OHH 100

// ---------------- device scratch (no allocs allowed) ----------------
__device__ float g_h[BB*NN*DD];
__device__ float g_x[BB*NN*3];
__device__ float g_frac[BB*NN*3];
__device__ float g_A[BB*NN*DD];
__device__ float g_Bv[BB*NN*DD];
__device__ float g_S[BB*NN*DD];
__device__ float g_invC[BB*9];

__device__ __forceinline__ float silu_f(float x){ return x / (1.f + __expf(-x)); }
__device__ __forceinline__ float sigm_f(float x){ return 1.f / (1.f + __expf(-x)); }

// ---------------- 3x3 inverse per batch ----------------
__global__ void k_inv(const float* __restrict__ cell){
    int b = threadIdx.x;
    if (b >= BB) return;
    const float* c = cell + b*9;
    float a00=c[0],a01=c[1],a02=c[2];
    float a10=c[3],a11=c[4],a12=c[5];
    float a20=c[6],a21=c[7],a22=c[8];
    float C00 =  a11*a22 - a12*a21;
    float C01 = -(a10*a22 - a12*a20);
    float C02 =  a10*a21 - a11*a20;
    float C10 = -(a01*a22 - a02*a21);
    float C11 =  a00*a22 - a02*a20;
    float C12 = -(a00*a21 - a01*a20);
    float C20 =  a01*a12 - a02*a11;
    float C21 = -(a00*a12 - a02*a10);
    float C22 =  a00*a11 - a01*a10;
    float det = a00*C00 + a01*C01 + a02*C02;
    float id = 1.f/det;
    float* o = g_invC + b*9;
    o[0]=C00*id; o[1]=C10*id; o[2]=C20*id;
    o[3]=C01*id; o[4]=C11*id; o[5]=C21*id;
    o[6]=C02*id; o[7]=C12*id; o[8]=C22*id;
}

__global__ void k_init(const float* __restrict__ pos){
    int t = blockIdx.x*blockDim.x + threadIdx.x;
    if (t < BB*NN*3) g_x[t] = pos[t];
}

// frac = x @ invC (one thread per atom)
__global__ void k_frac(){
    int idx = blockIdx.x*blockDim.x + threadIdx.x;
    if (idx >= BB*NN) return;
    int b = idx / NN;
    const float* ic = g_invC + b*9;
    float px=g_x[idx*3+0], py=g_x[idx*3+1], pz=g_x[idx*3+2];
    g_frac[idx*3+0] = px*ic[0] + py*ic[3] + pz*ic[6];
    g_frac[idx*3+1] = px*ic[1] + py*ic[4] + pz*ic[7];
    g_frac[idx*3+2] = px*ic[2] + py*ic[5] + pz*ic[8];
}

// input embedding: h = silu([pos,onehot]@W1+b1)@W2+b2
__global__ void k_embed(const float* __restrict__ pos, const float* __restrict__ oneh,
                        const float* __restrict__ W1, const float* __restrict__ b1,
                        const float* __restrict__ W2, const float* __restrict__ b2){
    int i = blockIdx.x, b = blockIdx.y, tid = threadIdx.x;
    __shared__ float sin_[OHH+3];
    __shared__ float sh1[DD];
    if (tid < OHH+3){
        sin_[tid] = (tid < 3) ? pos[(b*NN+i)*3 + tid] : oneh[(b*NN+i)*OHH + (tid-3)];
    }
    __syncthreads();
    float t = b1[tid];
    #pragma unroll 8
    for (int k = 0; k < OHH+3; k++) t += sin_[k]*W1[k*DD + tid];
    sh1[tid] = silu_f(t);
    __syncthreads();
    float t2 = b2[tid];
    #pragma unroll 8
    for (int k = 0; k < DD; k++) t2 += sh1[k]*W2[k*DD + tid];
    g_h[(b*NN+i)*DD + tid] = t2;
}

// A = h@We1[:D], Bv = h@We1[D:2D]
__global__ void k_A(const float* __restrict__ We1l){
    int i = blockIdx.x, b = blockIdx.y, tid = threadIdx.x;
    __shared__ float sh[DD];
    sh[tid] = g_h[(b*NN+i)*DD + tid];
    __syncthreads();
    float a = 0.f, bv = 0.f;
    #pragma unroll 8
    for (int k = 0; k < DD; k++){
        float hv = sh[k];
        a  += hv * We1l[k*DD + tid];
        bv += hv * We1l[(DD+k)*DD + tid];
    }
    g_A[(b*NN+i)*DD + tid]  = a;
    g_Bv[(b*NN+i)*DD + tid] = bv;
}

// -------- the heavy per-pair kernel: block = (b,i), loops j --------
__global__ void __launch_bounds__(128) k_edge(
    const float* __restrict__ We1l, const float* __restrict__ be1l,
    const float* __restrict__ We2l, const float* __restrict__ be2l,
    const float* __restrict__ We3l, const float* __restrict__ be3l,
    const float* __restrict__ Wm1l, const float* __restrict__ bm1l,
    const float* __restrict__ Wp1l, const float* __restrict__ bp1l,
    const float* __restrict__ Wp2l, const float* __restrict__ bp2l,
    const float* __restrict__ cell, const float* __restrict__ mask)
{
    int i = blockIdx.x, b = blockIdx.y, tid = threadIdx.x;
    __shared__ __align__(16) float sm1[DD];
    __shared__ float stb[DD];
    __shared__ float sred[4];
    __shared__ float sfi[3];
    __shared__ float scell[9];

    // We2 column tid resident in registers
    float wreg[DD];
    #pragma unroll
    for (int d = 0; d < DD; d++) wreg[d] = We2l[d*DD + tid];

    float wdreg = We1l[256*DD + tid];
    float be2r = be2l[tid], we3r = We3l[tid];
    float wm1r = Wm1l[tid], bm1r = bm1l[tid];
    float wp1r = Wp1l[tid], bp1r = bp1l[tid], wp2r = Wp2l[tid];
    float be3v = be3l[0],  bp2v = bp2l[0];

    stb[tid] = g_A[(b*NN+i)*DD + tid] + be1l[tid];
    if (tid < 3) sfi[tid] = g_frac[(b*NN+i)*3 + tid];
    if (tid < 9) scell[tid] = cell[b*9 + tid];
    float mi = mask[b*NN + i];
    __syncthreads();

    float fi0=sfi[0], fi1=sfi[1], fi2=sfi[2];
    float c0=scell[0],c1=scell[1],c2=scell[2];
    float c3=scell[3],c4=scell[4],c5=scell[5];
    float c6=scell[6],c7=scell[7],c8=scell[8];
    float tb = stb[tid];

    float Sacc = 0.f;
    float dxa0=0.f, dxa1=0.f, dxa2=0.f;
    float srx=0.f, sry=0.f, srz=0.f;

    for (int j = 0; j < NN; j++){
        float bvj = g_Bv[(b*NN+j)*DD + tid];
        float f0 = g_frac[(b*NN+j)*3+0] - fi0;
        float f1 = g_frac[(b*NN+j)*3+1] - fi1;
        float f2 = g_frac[(b*NN+j)*3+2] - fi2;
        f0 -= rintf(f0); f1 -= rintf(f1); f2 -= rintf(f2);
        float rx = f0*c0 + f1*c3 + f2*c6;
        float ry = f0*c1 + f1*c4 + f2*c7;
        float rz = f0*c2 + f1*c5 + f2*c8;
        float d2 = rx*rx + ry*ry + rz*rz + 1e-12f;
        float dij = sqrtf(d2);
        float pm = mi * mask[b*NN + j];
        dij = dij*pm + (1.f - pm)*1e6f;
        rx *= pm; ry *= pm; rz *= pm;

        float m1 = silu_f(tb + bvj + dij*wdreg);
        sm1[tid] = m1;
        __syncthreads();                        // B1: sm1 ready (also guards sred reuse)

        float a0=0.f,a1=0.f,a2=0.f,a3=0.f;
        const float4* mv = (const float4*)sm1;
        #pragma unroll
        for (int q = 0; q < 32; q++){
            float4 v = mv[q];
            a0 += v.x*wreg[4*q+0];
            a1 += v.y*wreg[4*q+1];
            a2 += v.z*wreg[4*q+2];
            a3 += v.w*wreg[4*q+3];
        }
        float m2 = silu_f(a0+a1+a2+a3 + be2r);
        float part = m2 * we3r;
        #pragma unroll
        for (int o = 16; o; o >>= 1) part += __shfl_xor_sync(0xffffffffu, part, o);
        if ((tid & 31) == 0) sred[tid >> 5] = part;
        __syncthreads();                        // B2: sred ready
        float mij = (sred[0]+sred[1]+sred[2]+sred[3] + be3v) * pm;

        Sacc += silu_f(mij*wm1r + bm1r);
        float p = silu_f(mij*wp1r + bp1r) * wp2r;
        dxa0 += rx*p; dxa1 += ry*p; dxa2 += rz*p;
        srx += rx; sry += ry; srz += rz;
    }

    g_S[(b*NN+i)*DD + tid] = Sacc;

    // reduce dx (3 components) over 128 threads; phi bias term: + bp2 * sum_j rij
    float vals[3] = {dxa0, dxa1, dxa2};
    float rsum[3] = {srx, sry, srz};
    for (int c = 0; c < 3; c++){
        float v = vals[c];
        #pragma unroll
        for (int o = 16; o; o >>= 1) v += __shfl_xor_sync(0xffffffffu, v, o);
        __syncthreads();
        if ((tid & 31) == 0) sred[tid >> 5] = v;
        __syncthreads();
        if (tid == 0){
            float tot = sred[0]+sred[1]+sred[2]+sred[3];
            g_x[(b*NN+i)*3 + c] += tot + bp2v * rsum[c];
        }
    }
}

// m_node GEMM (hoisted Wm2) + GRU cell
__global__ void k_node(const float* __restrict__ Wm2l, const float* __restrict__ bm2l,
                       const float* __restrict__ Wihl, const float* __restrict__ Whhl,
                       const float* __restrict__ bihl, const float* __restrict__ bhhl,
                       const float* __restrict__ mask){
    int i = blockIdx.x, b = blockIdx.y, tid = threadIdx.x;
    __shared__ float sS[DD], sh[DD], smn[DD];
    int idx = (b*NN+i)*DD + tid;
    sS[tid] = g_S[idx];
    sh[tid] = g_h[idx];
    __syncthreads();
    float mn = (float)NN * bm2l[tid];
    #pragma unroll 8
    for (int k = 0; k < DD; k++) mn += sS[k]*Wm2l[k*DD + tid];
    smn[tid] = mn;
    __syncthreads();
    float gir=bihl[tid], giz=bihl[DD+tid], gin=bihl[2*DD+tid];
    float ghr=bhhl[tid], ghz=bhhl[DD+tid], ghn=bhhl[2*DD+tid];
    #pragma unroll 4
    for (int k = 0; k < DD; k++){
        float mk = smn[k], hk = sh[k];
        gir += mk*Wihl[k*3*DD + tid];
        giz += mk*Wihl[k*3*DD + DD + tid];
        gin += mk*Wihl[k*3*DD + 2*DD + tid];
        ghr += hk*Whhl[k*3*DD + tid];
        ghz += hk*Whhl[k*3*DD + DD + tid];
        ghn += hk*Whhl[k*3*DD + 2*DD + tid];
    }
    float r = sigm_f(gir + ghr);
    float z = sigm_f(giz + ghz);
    float n = tanhf(gin + r*ghn);
    float hn = (1.f - z)*n + z*sh[tid];
    g_h[idx] = hn * mask[b*NN + i];
}

// mean-pool + head MLP + softplus/sigmoid
__global__ void k_pool(const float* __restrict__ mask,
                       const float* __restrict__ Wc1, const float* __restrict__ bc1,
                       const float* __restrict__ Wc2, const float* __restrict__ bc2,
                       const float* __restrict__ Wc3, const float* __restrict__ bc3,
                       float* __restrict__ out){
    int b = blockIdx.x, tid = threadIdx.x;
    __shared__ float feat[DD], o1[DD], o2[64];
    float s = 0.f, ms = 0.f;
    for (int i = 0; i < NN; i++){
        float mk = mask[b*NN + i];
        s  += g_h[(b*NN+i)*DD + tid]*mk;
        ms += mk;
    }
    feat[tid] = s / fmaxf(ms, 1.f);
    __syncthreads();
    float t = bc1[tid];
    #pragma unroll 8
    for (int k = 0; k < DD; k++) t += feat[k]*Wc1[k*DD + tid];
    o1[tid] = silu_f(t);
    __syncthreads();
    if (tid < 64){
        float t2 = bc2[tid];
        #pragma unroll 8
        for (int k = 0; k < DD; k++) t2 += o1[k]*Wc2[k*64 + tid];
        o2[tid] = silu_f(t2);
    }
    __syncthreads();
    if (tid < 6){
        float t3 = bc3[tid];
        #pragma unroll
        for (int k = 0; k < 64; k++) t3 += o2[k]*Wc3[k*6 + tid];
        float r;
        if (tid < 3){
            r = (t3 > 20.f) ? t3 : log1pf(expf(t3));      // softplus
        } else {
            r = (1.f / (1.f + expf(-t3))) * 180.f;        // sigmoid*180
        }
        out[b*6 + tid] = r;
    }
}

extern "C" void kernel_launch(void* const* d_in, const int* in_sizes, int n_in,
                              void* d_out, int out_size){
    const float* pos   = (const float*)d_in[0];
    const float* oneh  = (const float*)d_in[1];
    const float* mask  = (const float*)d_in[2];
    const float* cell  = (const float*)d_in[3];
    const float* W_in1 = (const float*)d_in[4];
    const float* b_in1 = (const float*)d_in[5];
    const float* W_in2 = (const float*)d_in[6];
    const float* b_in2 = (const float*)d_in[7];
    const float* We1   = (const float*)d_in[8];
    const float* be1   = (const float*)d_in[9];
    const float* We2   = (const float*)d_in[10];
    const float* be2   = (const float*)d_in[11];
    const float* We3   = (const float*)d_in[12];
    const float* be3   = (const float*)d_in[13];
    const float* Wm1   = (const float*)d_in[14];
    const float* bm1   = (const float*)d_in[15];
    const float* Wm2   = (const float*)d_in[16];
    const float* bm2   = (const float*)d_in[17];
    const float* Wp1   = (const float*)d_in[18];
    const float* bp1   = (const float*)d_in[19];
    const float* Wp2   = (const float*)d_in[20];
    const float* bp2   = (const float*)d_in[21];
    const float* W_ih  = (const float*)d_in[22];
    const float* W_hh  = (const float*)d_in[23];
    const float* b_ih  = (const float*)d_in[24];
    const float* b_hh  = (const float*)d_in[25];
    const float* Wc1   = (const float*)d_in[26];
    const float* bc1   = (const float*)d_in[27];
    const float* Wc2   = (const float*)d_in[28];
    const float* bc2   = (const float*)d_in[29];
    const float* Wc3   = (const float*)d_in[30];
    const float* bc3   = (const float*)d_in[31];
    float* out = (float*)d_out;

    dim3 gBN(NN, BB);

    k_inv<<<1, 32>>>(cell);
    k_init<<<(BB*NN*3 + 127)/128, 128>>>(pos);
    k_frac<<<(BB*NN + 127)/128, 128>>>();
    k_embed<<<gBN, 128>>>(pos, oneh, W_in1, b_in1, W_in2, b_in2);

    for (int l = 0; l < LL; l++){
        k_A<<<gBN, 128>>>(We1 + l*257*DD);
        k_edge<<<gBN, 128>>>(We1 + l*257*DD, be1 + l*DD,
                             We2 + l*DD*DD, be2 + l*DD,
                             We3 + l*DD,    be3 + l,
                             Wm1 + l*DD,    bm1 + l*DD,
                             Wp1 + l*DD,    bp1 + l*DD,
                             Wp2 + l*DD,    bp2 + l,
                             cell, mask);
        k_node<<<gBN, 128>>>(Wm2 + l*DD*DD, bm2 + l*DD,
                             W_ih + l*DD*3*DD, W_hh + l*DD*3*DD,
                             b_ih + l*3*DD,    b_hh + l*3*DD, mask);
        k_frac<<<(BB*NN + 127)/128, 128>>>();
    }

    k_pool<<<BB, 128>>>(mask, Wc1, bc1, Wc2, bc2, Wc3, bc3, out);
}

// round 2
// speedup vs baseline: 1.8462x; 1.8462x over previous
#include <cuda_runtime.h>
#include <math.h>

#define BB 2
#define NN 320
#define DD 128
#define LL 4
#define OHH 100
#define TS 64            // j-tile size in k_edge
#define SM1S 132         // sM1 row stride (floats), 16B-aligned, conflict-free

// ---------------- device scratch (no allocs allowed) ----------------
__device__ float g_h[BB*NN*DD];
__device__ float g_x[BB*NN*3];
__device__ float g_frac[BB*NN*3];
__device__ float g_A[BB*NN*DD];
__device__ float g_Bv[BB*NN*DD];
__device__ float g_S[BB*NN*DD];
__device__ float g_invC[BB*9];

__device__ __forceinline__ float silu_f(float x){ return x / (1.f + __expf(-x)); }
__device__ __forceinline__ float sigm_f(float x){ return 1.f / (1.f + __expf(-x)); }

// ---------------- 3x3 inverse per batch ----------------
__global__ void k_inv(const float* __restrict__ cell){
    int b = threadIdx.x;
    if (b >= BB) return;
    const float* c = cell + b*9;
    float a00=c[0],a01=c[1],a02=c[2];
    float a10=c[3],a11=c[4],a12=c[5];
    float a20=c[6],a21=c[7],a22=c[8];
    float C00 =  a11*a22 - a12*a21;
    float C01 = -(a10*a22 - a12*a20);
    float C02 =  a10*a21 - a11*a20;
    float C10 = -(a01*a22 - a02*a21);
    float C11 =  a00*a22 - a02*a20;
    float C12 = -(a00*a21 - a01*a20);
    float C20 =  a01*a12 - a02*a11;
    float C21 = -(a00*a12 - a02*a10);
    float C22 =  a00*a11 - a01*a10;
    float det = a00*C00 + a01*C01 + a02*C02;
    float id = 1.f/det;
    float* o = g_invC + b*9;
    o[0]=C00*id; o[1]=C10*id; o[2]=C20*id;
    o[3]=C01*id; o[4]=C11*id; o[5]=C21*id;
    o[6]=C02*id; o[7]=C12*id; o[8]=C22*id;
}

__global__ void k_init(const float* __restrict__ pos){
    int t = blockIdx.x*blockDim.x + threadIdx.x;
    if (t < BB*NN*3) g_x[t] = pos[t];
}

// frac = x @ invC (one thread per atom)
__global__ void k_frac(){
    int idx = blockIdx.x*blockDim.x + threadIdx.x;
    if (idx >= BB*NN) return;
    int b = idx / NN;
    const float* ic = g_invC + b*9;
    float px=g_x[idx*3+0], py=g_x[idx*3+1], pz=g_x[idx*3+2];
    g_frac[idx*3+0] = px*ic[0] + py*ic[3] + pz*ic[6];
    g_frac[idx*3+1] = px*ic[1] + py*ic[4] + pz*ic[7];
    g_frac[idx*3+2] = px*ic[2] + py*ic[5] + pz*ic[8];
}

// input embedding: h = silu([pos,onehot]@W1+b1)@W2+b2
__global__ void k_embed(const float* __restrict__ pos, const float* __restrict__ oneh,
                        const float* __restrict__ W1, const float* __restrict__ b1,
                        const float* __restrict__ W2, const float* __restrict__ b2){
    int i = blockIdx.x, b = blockIdx.y, tid = threadIdx.x;
    __shared__ float sin_[OHH+3];
    __shared__ float sh1[DD];
    if (tid < OHH+3){
        sin_[tid] = (tid < 3) ? pos[(b*NN+i)*3 + tid] : oneh[(b*NN+i)*OHH + (tid-3)];
    }
    __syncthreads();
    float t = b1[tid];
    #pragma unroll 8
    for (int k = 0; k < OHH+3; k++) t += sin_[k]*W1[k*DD + tid];
    sh1[tid] = silu_f(t);
    __syncthreads();
    float t2 = b2[tid];
    #pragma unroll 8
    for (int k = 0; k < DD; k++) t2 += sh1[k]*W2[k*DD + tid];
    g_h[(b*NN+i)*DD + tid] = t2;
}

// A = h@We1[:D], Bv = h@We1[D:2D]
__global__ void k_A(const float* __restrict__ We1l){
    int i = blockIdx.x, b = blockIdx.y, tid = threadIdx.x;
    __shared__ float sh[DD];
    sh[tid] = g_h[(b*NN+i)*DD + tid];
    __syncthreads();
    float a = 0.f, bv = 0.f;
    #pragma unroll 8
    for (int k = 0; k < DD; k++){
        float hv = sh[k];
        a  += hv * We1l[k*DD + tid];
        bv += hv * We1l[(DD+k)*DD + tid];
    }
    g_A[(b*NN+i)*DD + tid]  = a;
    g_Bv[(b*NN+i)*DD + tid] = bv;
}

// ======== heavy kernel: per-(b,i) fused 320x128x128 GEMM + epilogue ========
// 256 threads = 16x16 (ty, tx); C micro-tile 4j x 8t per thread.
// dynamic smem layout (floats):
//   sWe2 [128][128]            16384
//   sM1  [64][SM1S]             8448
//   sDij [320], sRx/Ry/Rz[320], sPm[320]   1600
//   sWt  [7][128] = be2,we3,wm1,bm1,wp1,bp1,wp2   896
//   sMij [64]                     64
//   sDx  [16][6]                  96
#define SMEM_FLOATS (16384 + 8448 + 1600 + 896 + 64 + 96)

__global__ void __launch_bounds__(256, 2) k_edge(
    const float* __restrict__ We1l, const float* __restrict__ be1l,
    const float* __restrict__ We2l, const float* __restrict__ be2l,
    const float* __restrict__ We3l, const float* __restrict__ be3l,
    const float* __restrict__ Wm1l, const float* __restrict__ bm1l,
    const float* __restrict__ Wp1l, const float* __restrict__ bp1l,
    const float* __restrict__ Wp2l, const float* __restrict__ bp2l,
    const float* __restrict__ cell, const float* __restrict__ mask)
{
    extern __shared__ float sm[];
    float* sWe2 = sm;                       // 16384
    float* sM1  = sWe2 + 16384;             // 8448
    float* sDij = sM1 + 8448;               // 320
    float* sRx  = sDij + 320;
    float* sRy  = sRx + 320;
    float* sRz  = sRy + 320;
    float* sPm  = sRz + 320;
    float* sWt  = sPm + 320;                // 896
    float* sMij = sWt + 896;                // 64
    float* sDx  = sMij + 64;                // 96

    int i = blockIdx.x, b = blockIdx.y;
    int tid = threadIdx.x;
    int tx = tid & 15, ty = tid >> 4;
    int lane5 = tid & 31;                   // k-column group owner for m1 phase
    int warpRow = tid >> 5;                 // 0..7

    // stage We2 (row-major [k][t]) into smem
    {
        const float4* W2v = (const float4*)We2l;
        float4* sW2v = (float4*)sWe2;
        #pragma unroll
        for (int q = 0; q < 16; q++) sW2v[tid + q*256] = W2v[tid + q*256];
    }
    // stage per-t weights
    if (tid < 128){
        sWt[tid]       = be2l[tid];
        sWt[128+tid]   = We3l[tid];
        sWt[256+tid]   = Wm1l[tid];
        sWt[384+tid]   = bm1l[tid];
        sWt[512+tid]   = Wp1l[tid];
        sWt[640+tid]   = bp1l[tid];
        sWt[768+tid]   = Wp2l[tid];
    }

    // geometry for all 320 j (min-image from read-only g_frac)
    float fi0 = g_frac[(b*NN+i)*3+0];
    float fi1 = g_frac[(b*NN+i)*3+1];
    float fi2 = g_frac[(b*NN+i)*3+2];
    float mi  = mask[b*NN + i];
    float c0=cell[b*9+0],c1=cell[b*9+1],c2=cell[b*9+2];
    float c3=cell[b*9+3],c4=cell[b*9+4],c5=cell[b*9+5];
    float c6=cell[b*9+6],c7=cell[b*9+7],c8=cell[b*9+8];
    for (int j = tid; j < NN; j += 256){
        float f0 = g_frac[(b*NN+j)*3+0] - fi0;
        float f1 = g_frac[(b*NN+j)*3+1] - fi1;
        float f2 = g_frac[(b*NN+j)*3+2] - fi2;
        f0 -= rintf(f0); f1 -= rintf(f1); f2 -= rintf(f2);
        float rx = f0*c0 + f1*c3 + f2*c6;
        float ry = f0*c1 + f1*c4 + f2*c7;
        float rz = f0*c2 + f1*c5 + f2*c8;
        float d2 = rx*rx + ry*ry + rz*rz + 1e-12f;
        float dij = sqrtf(d2);
        float pm = mi * mask[b*NN + j];
        sDij[j] = dij*pm + (1.f - pm)*1e6f;
        sRx[j] = rx*pm; sRy[j] = ry*pm; sRz[j] = rz*pm;
        sPm[j] = pm;
    }

    // per-thread m1 params: k columns 4*lane5 .. +3 (fixed for this thread)
    float4 tb4, wd4;
    {
        float4 A4   = *(const float4*)(g_A  + (b*NN+i)*DD + 4*lane5);
        float4 be14 = *(const float4*)(be1l + 4*lane5);
        tb4.x = A4.x + be14.x; tb4.y = A4.y + be14.y;
        tb4.z = A4.z + be14.z; tb4.w = A4.w + be14.w;
        wd4 = *(const float4*)(We1l + 256*DD + 4*lane5);
    }
    float be3v = be3l[0], bp2v = bp2l[0];

    float Sacc[8];
    #pragma unroll
    for (int t = 0; t < 8; t++) Sacc[t] = 0.f;
    float dxa0=0.f, dxa1=0.f, dxa2=0.f, sr0=0.f, sr1=0.f, sr2=0.f;

    __syncthreads();

    for (int jt = 0; jt < NN/TS; jt++){
        int j0 = jt*TS;
        // ---- m1 phase: tile [64 j][128 k] -> sM1[j][k] ----
        #pragma unroll
        for (int it = 0; it < 8; it++){
            int jj = it*8 + warpRow;
            int j  = j0 + jj;
            float4 bv = *(const float4*)(g_Bv + (b*NN+j)*DD + 4*lane5);
            float dij = sDij[j];
            float4 m;
            m.x = silu_f(tb4.x + bv.x + dij*wd4.x);
            m.y = silu_f(tb4.y + bv.y + dij*wd4.y);
            m.z = silu_f(tb4.z + bv.z + dij*wd4.z);
            m.w = silu_f(tb4.w + bv.w + dij*wd4.w);
            *(float4*)(sM1 + jj*SM1S + 4*lane5) = m;
        }
        __syncthreads();   // B1: sM1 ready

        // ---- GEMM: C[4j][8t] over k=128 ----
        float C[4][8];
        #pragma unroll
        for (int jj = 0; jj < 4; jj++)
            #pragma unroll
            for (int tt = 0; tt < 8; tt++) C[jj][tt] = 0.f;

        const float* a0p = sM1 + (ty*4+0)*SM1S;
        const float* a1p = sM1 + (ty*4+1)*SM1S;
        const float* a2p = sM1 + (ty*4+2)*SM1S;
        const float* a3p = sM1 + (ty*4+3)*SM1S;
        #pragma unroll 8
        for (int k = 0; k < DD; k++){
            float a0 = a0p[k], a1 = a1p[k], a2 = a2p[k], a3 = a3p[k];
            float4 b0 = *(const float4*)(sWe2 + k*DD + tx*8);
            float4 b1 = *(const float4*)(sWe2 + k*DD + tx*8 + 4);
            C[0][0]+=a0*b0.x; C[0][1]+=a0*b0.y; C[0][2]+=a0*b0.z; C[0][3]+=a0*b0.w;
            C[0][4]+=a0*b1.x; C[0][5]+=a0*b1.y; C[0][6]+=a0*b1.z; C[0][7]+=a0*b1.w;
            C[1][0]+=a1*b0.x; C[1][1]+=a1*b0.y; C[1][2]+=a1*b0.z; C[1][3]+=a1*b0.w;
            C[1][4]+=a1*b1.x; C[1][5]+=a1*b1.y; C[1][6]+=a1*b1.z; C[1][7]+=a1*b1.w;
            C[2][0]+=a2*b0.x; C[2][1]+=a2*b0.y; C[2][2]+=a2*b0.z; C[2][3]+=a2*b0.w;
            C[2][4]+=a2*b1.x; C[2][5]+=a2*b1.y; C[2][6]+=a2*b1.z; C[2][7]+=a2*b1.w;
            C[3][0]+=a3*b0.x; C[3][1]+=a3*b0.y; C[3][2]+=a3*b0.z; C[3][3]+=a3*b0.w;
            C[3][4]+=a3*b1.x; C[3][5]+=a3*b1.y; C[3][6]+=a3*b1.z; C[3][7]+=a3*b1.w;
        }

        // ---- m2 = silu(C + be2), partial We3 dot per j ----
        float prt[4];
        #pragma unroll
        for (int jj = 0; jj < 4; jj++){
            float s = 0.f;
            #pragma unroll
            for (int tt = 0; tt < 8; tt++){
                int t = tx*8 + tt;
                float m2 = silu_f(C[jj][tt] + sWt[t]);
                s += m2 * sWt[128 + t];
            }
            prt[jj] = s;
        }
        #pragma unroll
        for (int o = 1; o < 16; o <<= 1){
            prt[0] += __shfl_xor_sync(0xffffffffu, prt[0], o);
            prt[1] += __shfl_xor_sync(0xffffffffu, prt[1], o);
            prt[2] += __shfl_xor_sync(0xffffffffu, prt[2], o);
            prt[3] += __shfl_xor_sync(0xffffffffu, prt[3], o);
        }
        if (tx == 0){
            #pragma unroll
            for (int jj = 0; jj < 4; jj++){
                int j = j0 + ty*4 + jj;
                sMij[ty*4 + jj] = (prt[jj] + be3v) * sPm[j];
            }
        }
        __syncthreads();   // B2: sMij ready

        // ---- Sacc and phi accumulation ----
        float pprt[4];
        #pragma unroll
        for (int jj = 0; jj < 4; jj++){
            float mij = sMij[ty*4 + jj];
            float psum = 0.f;
            #pragma unroll
            for (int tt = 0; tt < 8; tt++){
                int t = tx*8 + tt;
                Sacc[tt] += silu_f(mij*sWt[256+t] + sWt[384+t]);
                psum += silu_f(mij*sWt[512+t] + sWt[640+t]) * sWt[768+t];
            }
            pprt[jj] = psum;
        }
        #pragma unroll
        for (int o = 1; o < 16; o <<= 1){
            pprt[0] += __shfl_xor_sync(0xffffffffu, pprt[0], o);
            pprt[1] += __shfl_xor_sync(0xffffffffu, pprt[1], o);
            pprt[2] += __shfl_xor_sync(0xffffffffu, pprt[2], o);
            pprt[3] += __shfl_xor_sync(0xffffffffu, pprt[3], o);
        }
        if (tx == 0){
            #pragma unroll
            for (int jj = 0; jj < 4; jj++){
                int j = j0 + ty*4 + jj;
                float rx = sRx[j], ry = sRy[j], rz = sRz[j];
                float p = pprt[jj];
                dxa0 += rx*p; dxa1 += ry*p; dxa2 += rz*p;
                sr0 += rx; sr1 += ry; sr2 += rz;
            }
        }
        __syncthreads();   // B3: protect sM1/sMij for next tile
    }

    // ---- final Sacc reduction over the 16 ty groups ----
    float* sRed = sM1;   // reuse, needs 16*128 floats
    #pragma unroll
    for (int tt = 0; tt < 8; tt++) sRed[ty*DD + tx*8 + tt] = Sacc[tt];
    if (tx == 0){
        sDx[ty*6+0] = dxa0; sDx[ty*6+1] = dxa1; sDx[ty*6+2] = dxa2;
        sDx[ty*6+3] = sr0;  sDx[ty*6+4] = sr1;  sDx[ty*6+5] = sr2;
    }
    __syncthreads();
    if (tid < DD){
        float s = 0.f;
        #pragma unroll
        for (int r = 0; r < 16; r++) s += sRed[r*DD + tid];
        g_S[(b*NN+i)*DD + tid] = s;
    }
    if (tid == 0){
        float d0=0.f,d1=0.f,d2=0.f,s0=0.f,s1=0.f,s2=0.f;
        #pragma unroll
        for (int r = 0; r < 16; r++){
            d0 += sDx[r*6+0]; d1 += sDx[r*6+1]; d2 += sDx[r*6+2];
            s0 += sDx[r*6+3]; s1 += sDx[r*6+4]; s2 += sDx[r*6+5];
        }
        g_x[(b*NN+i)*3+0] += d0 + bp2v*s0;
        g_x[(b*NN+i)*3+1] += d1 + bp2v*s1;
        g_x[(b*NN+i)*3+2] += d2 + bp2v*s2;
    }
}

// m_node GEMM (hoisted Wm2) + GRU cell
__global__ void k_node(const float* __restrict__ Wm2l, const float* __restrict__ bm2l,
                       const float* __restrict__ Wihl, const float* __restrict__ Whhl,
                       const float* __restrict__ bihl, const float* __restrict__ bhhl,
                       const float* __restrict__ mask){
    int i = blockIdx.x, b = blockIdx.y, tid = threadIdx.x;
    __shared__ float sS[DD], sh[DD], smn[DD];
    int idx = (b*NN+i)*DD + tid;
    sS[tid] = g_S[idx];
    sh[tid] = g_h[idx];
    __syncthreads();
    float mn = (float)NN * bm2l[tid];
    #pragma unroll 8
    for (int k = 0; k < DD; k++) mn += sS[k]*Wm2l[k*DD + tid];
    smn[tid] = mn;
    __syncthreads();
    float gir=bihl[tid], giz=bihl[DD+tid], gin=bihl[2*DD+tid];
    float ghr=bhhl[tid], ghz=bhhl[DD+tid], ghn=bhhl[2*DD+tid];
    #pragma unroll 4
    for (int k = 0; k < DD; k++){
        float mk = smn[k], hk = sh[k];
        gir += mk*Wihl[k*3*DD + tid];
        giz += mk*Wihl[k*3*DD + DD + tid];
        gin += mk*Wihl[k*3*DD + 2*DD + tid];
        ghr += hk*Whhl[k*3*DD + tid];
        ghz += hk*Whhl[k*3*DD + DD + tid];
        ghn += hk*Whhl[k*3*DD + 2*DD + tid];
    }
    float r = sigm_f(gir + ghr);
    float z = sigm_f(giz + ghz);
    float n = tanhf(gin + r*ghn);
    float hn = (1.f - z)*n + z*sh[tid];
    g_h[idx] = hn * mask[b*NN + i];
}

// mean-pool + head MLP + softplus/sigmoid
__global__ void k_pool(const float* __restrict__ mask,
                       const float* __restrict__ Wc1, const float* __restrict__ bc1,
                       const float* __restrict__ Wc2, const float* __restrict__ bc2,
                       const float* __restrict__ Wc3, const float* __restrict__ bc3,
                       float* __restrict__ out){
    int b = blockIdx.x, tid = threadIdx.x;
    __shared__ float feat[DD], o1[DD], o2[64];
    float s = 0.f, ms = 0.f;
    for (int i = 0; i < NN; i++){
        float mk = mask[b*NN + i];
        s  += g_h[(b*NN+i)*DD + tid]*mk;
        ms += mk;
    }
    feat[tid] = s / fmaxf(ms, 1.f);
    __syncthreads();
    float t = bc1[tid];
    #pragma unroll 8
    for (int k = 0; k < DD; k++) t += feat[k]*Wc1[k*DD + tid];
    o1[tid] = silu_f(t);
    __syncthreads();
    if (tid < 64){
        float t2 = bc2[tid];
        #pragma unroll 8
        for (int k = 0; k < DD; k++) t2 += o1[k]*Wc2[k*64 + tid];
        o2[tid] = silu_f(t2);
    }
    __syncthreads();
    if (tid < 6){
        float t3 = bc3[tid];
        #pragma unroll
        for (int k = 0; k < 64; k++) t3 += o2[k]*Wc3[k*6 + tid];
        float r;
        if (tid < 3){
            r = (t3 > 20.f) ? t3 : log1pf(expf(t3));      // softplus
        } else {
            r = (1.f / (1.f + expf(-t3))) * 180.f;        // sigmoid*180
        }
        out[b*6 + tid] = r;
    }
}

extern "C" void kernel_launch(void* const* d_in, const int* in_sizes, int n_in,
                              void* d_out, int out_size){
    const float* pos   = (const float*)d_in[0];
    const float* oneh  = (const float*)d_in[1];
    const float* mask  = (const float*)d_in[2];
    const float* cell  = (const float*)d_in[3];
    const float* W_in1 = (const float*)d_in[4];
    const float* b_in1 = (const float*)d_in[5];
    const float* W_in2 = (const float*)d_in[6];
    const float* b_in2 = (const float*)d_in[7];
    const float* We1   = (const float*)d_in[8];
    const float* be1   = (const float*)d_in[9];
    const float* We2   = (const float*)d_in[10];
    const float* be2   = (const float*)d_in[11];
    const float* We3   = (const float*)d_in[12];
    const float* be3   = (const float*)d_in[13];
    const float* Wm1   = (const float*)d_in[14];
    const float* bm1   = (const float*)d_in[15];
    const float* Wm2   = (const float*)d_in[16];
    const float* bm2   = (const float*)d_in[17];
    const float* Wp1   = (const float*)d_in[18];
    const float* bp1   = (const float*)d_in[19];
    const float* Wp2   = (const float*)d_in[20];
    const float* bp2   = (const float*)d_in[21];
    const float* W_ih  = (const float*)d_in[22];
    const float* W_hh  = (const float*)d_in[23];
    const float* b_ih  = (const float*)d_in[24];
    const float* b_hh  = (const float*)d_in[25];
    const float* Wc1   = (const float*)d_in[26];
    const float* bc1   = (const float*)d_in[27];
    const float* Wc2   = (const float*)d_in[28];
    const float* bc2   = (const float*)d_in[29];
    const float* Wc3   = (const float*)d_in[30];
    const float* bc3   = (const float*)d_in[31];
    float* out = (float*)d_out;

    const int smemBytes = SMEM_FLOATS * (int)sizeof(float);
    cudaFuncSetAttribute(k_edge, cudaFuncAttributeMaxDynamicSharedMemorySize, smemBytes);

    dim3 gBN(NN, BB);

    k_inv<<<1, 32>>>(cell);
    k_init<<<(BB*NN*3 + 127)/128, 128>>>(pos);
    k_frac<<<(BB*NN + 127)/128, 128>>>();
    k_embed<<<gBN, 128>>>(pos, oneh, W_in1, b_in1, W_in2, b_in2);

    for (int l = 0; l < LL; l++){
        k_A<<<gBN, 128>>>(We1 + l*257*DD);
        k_edge<<<gBN, 256, smemBytes>>>(We1 + l*257*DD, be1 + l*DD,
                             We2 + l*DD*DD, be2 + l*DD,
                             We3 + l*DD,    be3 + l,
                             Wm1 + l*DD,    bm1 + l*DD,
                             Wp1 + l*DD,    bp1 + l*DD,
                             Wp2 + l*DD,    bp2 + l,
                             cell, mask);
        k_node<<<gBN, 128>>>(Wm2 + l*DD*DD, bm2 + l*DD,
                             W_ih + l*DD*3*DD, W_hh + l*DD*3*DD,
                             b_ih + l*3*DD,    b_hh + l*3*DD, mask);
        k_frac<<<(BB*NN + 127)/128, 128>>>();
    }

    k_pool<<<BB, 128>>>(mask, Wc1, bc1, Wc2, bc2, Wc3, bc3, out);
}

// round 4
// speedup vs baseline: 4.1667x; 2.2569x over previous
#include <cuda_runtime.h>
#include <cuda_bf16.h>
#include <math.h>
#include <stdint.h>

#define BB 2
#define NN 320
#define DD 128
#define LL 4
#define OHH 100
#define KS 136   // smem row stride in bf16 elems (272 bytes)

// ---------------- device scratch (no allocs allowed) ----------------
__device__ float g_h[BB*NN*DD];
__device__ float g_x[BB*NN*3];
__device__ float g_frac[BB*NN*3];
__device__ float g_A[BB*NN*DD];
__device__ float g_Bv[BB*NN*DD];
__device__ float g_S[BB*NN*DD];
__device__ float g_invC[BB*9];
__device__ unsigned short g_We2bf[LL*DD*DD];   // per-layer B[n][k] = We2[k][n] in bf16

// ---------------- math helpers ----------------
__device__ __forceinline__ float tanh_ap(float x){
    float t; asm("tanh.approx.f32 %0, %1;" : "=f"(t) : "f"(x)); return t;
}
__device__ __forceinline__ float silu_f(float x){
    return 0.5f*x*(1.f + tanh_ap(0.5f*x));
}
__device__ __forceinline__ float sigm_f(float x){
    return 0.5f*(1.f + tanh_ap(0.5f*x));
}

__device__ __forceinline__ uint32_t smem_u32(const void* p){
    uint32_t a;
    asm("{ .reg .u64 t; cvta.to.shared.u64 t, %1; cvt.u32.u64 %0, t; }" : "=r"(a) : "l"(p));
    return a;
}
__device__ __forceinline__ void ldsm4(uint32_t& r0, uint32_t& r1, uint32_t& r2, uint32_t& r3, uint32_t a){
    asm volatile("ldmatrix.sync.aligned.m8n8.x4.shared.b16 {%0,%1,%2,%3}, [%4];"
                 : "=r"(r0),"=r"(r1),"=r"(r2),"=r"(r3) : "r"(a));
}
__device__ __forceinline__ void mma16816(float* c, uint32_t a0,uint32_t a1,uint32_t a2,uint32_t a3,
                                         uint32_t b0,uint32_t b1){
    asm volatile("mma.sync.aligned.m16n8k16.row.col.f32.bf16.bf16.f32 "
        "{%0,%1,%2,%3}, {%4,%5,%6,%7}, {%8,%9}, {%0,%1,%2,%3};"
        : "+f"(c[0]),"+f"(c[1]),"+f"(c[2]),"+f"(c[3])
        : "r"(a0),"r"(a1),"r"(a2),"r"(a3),"r"(b0),"r"(b1));
}

// ---------------- small kernels ----------------
__global__ void k_inv(const float* __restrict__ cell){
    int b = threadIdx.x;
    if (b >= BB) return;
    const float* c = cell + b*9;
    float a00=c[0],a01=c[1],a02=c[2];
    float a10=c[3],a11=c[4],a12=c[5];
    float a20=c[6],a21=c[7],a22=c[8];
    float C00 =  a11*a22 - a12*a21;
    float C01 = -(a10*a22 - a12*a20);
    float C02 =  a10*a21 - a11*a20;
    float C10 = -(a01*a22 - a02*a21);
    float C11 =  a00*a22 - a02*a20;
    float C12 = -(a00*a21 - a01*a20);
    float C20 =  a01*a12 - a02*a11;
    float C21 = -(a00*a12 - a02*a10);
    float C22 =  a00*a11 - a01*a10;
    float det = a00*C00 + a01*C01 + a02*C02;
    float id = 1.f/det;
    float* o = g_invC + b*9;
    o[0]=C00*id; o[1]=C10*id; o[2]=C20*id;
    o[3]=C01*id; o[4]=C11*id; o[5]=C21*id;
    o[6]=C02*id; o[7]=C12*id; o[8]=C22*id;
}

__global__ void k_init(const float* __restrict__ pos){
    int t = blockIdx.x*blockDim.x + threadIdx.x;
    if (t < BB*NN*3) g_x[t] = pos[t];
}

__global__ void k_frac(){
    int idx = blockIdx.x*blockDim.x + threadIdx.x;
    if (idx >= BB*NN) return;
    int b = idx / NN;
    const float* ic = g_invC + b*9;
    float px=g_x[idx*3+0], py=g_x[idx*3+1], pz=g_x[idx*3+2];
    g_frac[idx*3+0] = px*ic[0] + py*ic[3] + pz*ic[6];
    g_frac[idx*3+1] = px*ic[1] + py*ic[4] + pz*ic[7];
    g_frac[idx*3+2] = px*ic[2] + py*ic[5] + pz*ic[8];
}

// prepare We2^T bf16: B[n][k] = We2[k][n]
__global__ void k_prepW(const float* __restrict__ We2){
    int l = blockIdx.x, tid = threadIdx.x;
    const float* W = We2 + l*DD*DD;
    unsigned short* dst = g_We2bf + l*DD*DD;
    for (int e = tid; e < DD*DD; e += 256){
        int n = e >> 7, k = e & 127;
        dst[e] = __bfloat16_as_ushort(__float2bfloat16_rn(W[k*DD + n]));
    }
}

__global__ void k_embed(const float* __restrict__ pos, const float* __restrict__ oneh,
                        const float* __restrict__ W1, const float* __restrict__ b1,
                        const float* __restrict__ W2, const float* __restrict__ b2){
    int i = blockIdx.x, b = blockIdx.y, tid = threadIdx.x;
    __shared__ float sin_[OHH+3];
    __shared__ float sh1[DD];
    if (tid < OHH+3){
        sin_[tid] = (tid < 3) ? pos[(b*NN+i)*3 + tid] : oneh[(b*NN+i)*OHH + (tid-3)];
    }
    __syncthreads();
    float t = b1[tid];
    #pragma unroll 8
    for (int k = 0; k < OHH+3; k++) t += sin_[k]*W1[k*DD + tid];
    sh1[tid] = silu_f(t);
    __syncthreads();
    float t2 = b2[tid];
    #pragma unroll 8
    for (int k = 0; k < DD; k++) t2 += sh1[k]*W2[k*DD + tid];
    g_h[(b*NN+i)*DD + tid] = t2;
}

__global__ void k_A(const float* __restrict__ We1l){
    int i = blockIdx.x, b = blockIdx.y, tid = threadIdx.x;
    __shared__ float sh[DD];
    sh[tid] = g_h[(b*NN+i)*DD + tid];
    __syncthreads();
    float a = 0.f, bv = 0.f;
    #pragma unroll 8
    for (int k = 0; k < DD; k++){
        float hv = sh[k];
        a  += hv * We1l[k*DD + tid];
        bv += hv * We1l[(DD+k)*DD + tid];
    }
    g_A[(b*NN+i)*DD + tid]  = a;
    g_Bv[(b*NN+i)*DD + tid] = bv;
}

// ---------------- heavy kernel: mma.sync per (b,i) ----------------
// dynamic smem byte offsets:
#define OFF_B    0                       // bf16 [128][KS]  = 34816 B
#define OFF_M1   34816                   // bf16 [128][KS]  = 34816 B
#define OFF_GEO  69632                   // 5 x 384 floats  = 7680 B
#define OFF_WT   77312                   // 1152 floats     = 4608 B
#define OFF_MIJ  81920                   // 384 floats      = 1536 B
#define OFF_PART 83456                   // 256 floats      = 1024 B
#define SMEMB    84480

__global__ void __launch_bounds__(256, 2) k_edge(
    const float* __restrict__ We1l, const float* __restrict__ be1l,
    const float* __restrict__ be2l, const float* __restrict__ We3l,
    const float* __restrict__ be3l,
    const float* __restrict__ Wm1l, const float* __restrict__ bm1l,
    const float* __restrict__ Wp1l, const float* __restrict__ bp1l,
    const float* __restrict__ Wp2l, const float* __restrict__ bp2l,
    const float* __restrict__ cell, const float* __restrict__ mask, int layer)
{
    extern __shared__ char base[];
    __nv_bfloat16* sB  = (__nv_bfloat16*)(base + OFF_B);
    __nv_bfloat16* sM1 = (__nv_bfloat16*)(base + OFF_M1);
    float* sDij = (float*)(base + OFF_GEO);
    float* sRx  = sDij + 384;
    float* sRy  = sRx + 384;
    float* sRz  = sRy + 384;
    float* sPm  = sRz + 384;
    float* sWt  = (float*)(base + OFF_WT);
    float* sMij = (float*)(base + OFF_MIJ);
    float* sPart= (float*)(base + OFF_PART);

    int i = blockIdx.x, b = blockIdx.y;
    int tid = threadIdx.x, wid = tid >> 5, lane = tid & 31;

    // stage B[n][k] bf16 into padded smem (uint4 chunks of 8 bf16)
    {
        const uint4* src = (const uint4*)(g_We2bf + layer*DD*DD);
        #pragma unroll
        for (int q = 0; q < 8; q++){
            int e = tid + q*256;            // chunk id: n = e/16, k0 = (e%16)*8
            int n = e >> 4, k0 = (e & 15) << 3;
            *(uint4*)(sB + n*KS + k0) = src[e];
        }
    }
    if (tid < 128){
        sWt[tid]       = be2l[tid];
        sWt[128+tid]   = We3l[tid];
        sWt[256+tid]   = Wm1l[tid];
        sWt[384+tid]   = bm1l[tid];
        sWt[512+tid]   = Wp1l[tid];
        sWt[640+tid]   = bp1l[tid];
        sWt[768+tid]   = Wp2l[tid];
        sWt[896+tid]   = g_A[(b*NN+i)*DD + tid] + be1l[tid];   // tb
        sWt[1024+tid]  = We1l[256*DD + tid];                    // wd
    }
    // geometry for all j (padded to 384)
    {
        float fi0 = g_frac[(b*NN+i)*3+0];
        float fi1 = g_frac[(b*NN+i)*3+1];
        float fi2 = g_frac[(b*NN+i)*3+2];
        float mi  = mask[b*NN + i];
        float c0=cell[b*9+0],c1=cell[b*9+1],c2=cell[b*9+2];
        float c3=cell[b*9+3],c4=cell[b*9+4],c5=cell[b*9+5];
        float c6=cell[b*9+6],c7=cell[b*9+7],c8=cell[b*9+8];
        for (int j = tid; j < 384; j += 256){
            if (j < NN){
                float f0 = g_frac[(b*NN+j)*3+0] - fi0;
                float f1 = g_frac[(b*NN+j)*3+1] - fi1;
                float f2 = g_frac[(b*NN+j)*3+2] - fi2;
                f0 -= rintf(f0); f1 -= rintf(f1); f2 -= rintf(f2);
                float rx = f0*c0 + f1*c3 + f2*c6;
                float ry = f0*c1 + f1*c4 + f2*c7;
                float rz = f0*c2 + f1*c5 + f2*c8;
                float dij = sqrtf(rx*rx + ry*ry + rz*rz + 1e-12f);
                float pm = mi * mask[b*NN + j];
                sDij[j] = dij*pm + (1.f - pm)*1e6f;
                sRx[j] = rx*pm; sRy[j] = ry*pm; sRz[j] = rz*pm;
                sPm[j] = pm;
            } else {
                sDij[j]=0.f; sRx[j]=0.f; sRy[j]=0.f; sRz[j]=0.f; sPm[j]=0.f;
            }
        }
    }
    __syncthreads();

    float be3v = be3l[0], bp2v = bp2l[0];

    // warp tiling: wm = M offset (j), wn = N offset (t)
    int wm = (wid >> 1) * 32;
    int wn = (wid & 1) * 64;

    // ldmatrix lane base addresses (byte), advanced by 32B per k-step
    uint32_t sM1a = smem_u32(sM1);
    uint32_t sBa  = smem_u32(sB);
    int lr = lane & 7;
    int lb3 = (lane >> 3) & 1;
    int lb4 = lane >> 4;
    uint32_t aBase0 = sM1a + (uint32_t)(((wm + lr + lb3*8)*KS + lb4*8) * 2);
    uint32_t aBase1 = aBase0 + 16*KS*2;
    uint32_t bBase[4];
    #pragma unroll
    for (int ntp = 0; ntp < 4; ntp++)
        bBase[ntp] = sBa + (uint32_t)(((wn + (ntp*2 + lb4)*8 + lr)*KS + lb3*8) * 2);

    for (int T = 0; T < 3; T++){
        // ---- m1 phase: all 256 threads build tile [128 j][128 k] bf16 ----
        {
            int j_loc = tid >> 1;
            int khalf = (tid & 1) * 64;
            int jg = T*128 + j_loc;
            __nv_bfloat16* row = sM1 + j_loc*KS + khalf;
            if (jg < NN){
                float dij = sDij[jg];
                const float* bv = g_Bv + (size_t)(b*NN + jg)*DD + khalf;
                const float* tb = sWt + 896 + khalf;
                const float* wd = sWt + 1024 + khalf;
                #pragma unroll
                for (int u = 0; u < 8; u++){
                    uint32_t p[4];
                    #pragma unroll
                    for (int q = 0; q < 4; q++){
                        int k = u*8 + q*2;
                        float lo = silu_f(tb[k]   + bv[k]   + dij*wd[k]);
                        float hi = silu_f(tb[k+1] + bv[k+1] + dij*wd[k+1]);
                        p[q] = (uint32_t)__bfloat16_as_ushort(__float2bfloat16_rn(lo))
                             | ((uint32_t)__bfloat16_as_ushort(__float2bfloat16_rn(hi)) << 16);
                    }
                    *(uint4*)(row + u*8) = make_uint4(p[0], p[1], p[2], p[3]);
                }
            } else {
                #pragma unroll
                for (int u = 0; u < 8; u++)
                    *(uint4*)(row + u*8) = make_uint4(0,0,0,0);
            }
        }
        __syncthreads();   // M1 tile ready

        // ---- GEMM: warp computes C[32 j][64 t] ----
        float acc[2][8][4];
        #pragma unroll
        for (int mi = 0; mi < 2; mi++)
            #pragma unroll
            for (int nt = 0; nt < 8; nt++)
                #pragma unroll
                for (int c = 0; c < 4; c++) acc[mi][nt][c] = 0.f;

        uint32_t aA0 = aBase0, aA1 = aBase1;
        uint32_t bA0 = bBase[0], bA1 = bBase[1], bA2 = bBase[2], bA3 = bBase[3];
        #pragma unroll
        for (int ks = 0; ks < 8; ks++){
            uint32_t a0,a1,a2,a3, a4,a5,a6,a7;
            ldsm4(a0,a1,a2,a3, aA0);
            ldsm4(a4,a5,a6,a7, aA1);
            uint32_t b0,b1,b2,b3;
            ldsm4(b0,b1,b2,b3, bA0);
            mma16816(acc[0][0], a0,a1,a2,a3, b0,b1);
            mma16816(acc[1][0], a4,a5,a6,a7, b0,b1);
            mma16816(acc[0][1], a0,a1,a2,a3, b2,b3);
            mma16816(acc[1][1], a4,a5,a6,a7, b2,b3);
            ldsm4(b0,b1,b2,b3, bA1);
            mma16816(acc[0][2], a0,a1,a2,a3, b0,b1);
            mma16816(acc[1][2], a4,a5,a6,a7, b0,b1);
            mma16816(acc[0][3], a0,a1,a2,a3, b2,b3);
            mma16816(acc[1][3], a4,a5,a6,a7, b2,b3);
            ldsm4(b0,b1,b2,b3, bA2);
            mma16816(acc[0][4], a0,a1,a2,a3, b0,b1);
            mma16816(acc[1][4], a4,a5,a6,a7, b0,b1);
            mma16816(acc[0][5], a0,a1,a2,a3, b2,b3);
            mma16816(acc[1][5], a4,a5,a6,a7, b2,b3);
            ldsm4(b0,b1,b2,b3, bA3);
            mma16816(acc[0][6], a0,a1,a2,a3, b0,b1);
            mma16816(acc[1][6], a4,a5,a6,a7, b0,b1);
            mma16816(acc[0][7], a0,a1,a2,a3, b2,b3);
            mma16816(acc[1][7], a4,a5,a6,a7, b2,b3);
            aA0 += 32; aA1 += 32; bA0 += 32; bA1 += 32; bA2 += 32; bA3 += 32;
        }

        // ---- epilogue: m2 = silu(C + be2), dot with we3 per j ----
        int colq = wn + (lane & 3)*2;
        #pragma unroll
        for (int mi = 0; mi < 2; mi++){
            float d0 = 0.f, d1 = 0.f;
            #pragma unroll
            for (int nt = 0; nt < 8; nt++){
                int col = colq + nt*8;
                float w0 = sWt[128+col], w1 = sWt[128+col+1];
                float e0 = sWt[col], e1 = sWt[col+1];
                d0 += silu_f(acc[mi][nt][0] + e0)*w0 + silu_f(acc[mi][nt][1] + e1)*w1;
                d1 += silu_f(acc[mi][nt][2] + e0)*w0 + silu_f(acc[mi][nt][3] + e1)*w1;
            }
            d0 += __shfl_xor_sync(0xffffffffu, d0, 1);
            d0 += __shfl_xor_sync(0xffffffffu, d0, 2);
            d1 += __shfl_xor_sync(0xffffffffu, d1, 1);
            d1 += __shfl_xor_sync(0xffffffffu, d1, 2);
            if ((lane & 3) == 0){
                int row = wm + mi*16 + (lane >> 2);
                sPart[(wid & 1)*128 + row]     = d0;
                sPart[(wid & 1)*128 + row + 8] = d1;
            }
        }
        __syncthreads();
        if (tid < 128){
            int j = T*128 + tid;
            sMij[j] = (sPart[tid] + sPart[128+tid] + be3v) * sPm[j];
        }
        __syncthreads();
    }

    // -------- final epilogue --------
    // Sacc[t] = sum_j silu(mij*wm1[t]+bm1[t]), j split in 2 halves of 160
    {
        int t = tid & 127, half = tid >> 7;
        float wm1 = sWt[256+t], bm1 = sWt[384+t];
        float s = 0.f;
        const float* mp = sMij + half*160;
        #pragma unroll 4
        for (int jj = 0; jj < 160; jj++)
            s += silu_f(fmaf(mp[jj], wm1, bm1));
        sPart[tid] = s;
    }
    // phi_j and coordinate deltas
    float dx0=0.f,dx1=0.f,dx2=0.f, sr0=0.f,sr1=0.f,sr2=0.f;
    #pragma unroll
    for (int rep = 0; rep < 2; rep++){
        int j = tid + rep*256;
        if (j < NN){
            float mij = sMij[j];
            float inner = 0.f;
            #pragma unroll 4
            for (int t2 = 0; t2 < 128; t2++)
                inner += silu_f(fmaf(mij, sWt[512+t2], sWt[640+t2])) * sWt[768+t2];
            dx0 += sRx[j]*inner; dx1 += sRy[j]*inner; dx2 += sRz[j]*inner;
            sr0 += sRx[j]; sr1 += sRy[j]; sr2 += sRz[j];
        }
    }
    __syncthreads();
    if (tid < 128) g_S[(b*NN+i)*DD + tid] = sPart[tid] + sPart[128+tid];

    // block-reduce 6 values
    float v[6] = {dx0,dx1,dx2,sr0,sr1,sr2};
    #pragma unroll
    for (int c = 0; c < 6; c++)
        #pragma unroll
        for (int o = 16; o; o >>= 1) v[c] += __shfl_xor_sync(0xffffffffu, v[c], o);
    if (lane == 0){
        #pragma unroll
        for (int c = 0; c < 6; c++) sMij[wid*6 + c] = v[c];
    }
    __syncthreads();
    if (tid == 0){
        float a0=0,a1=0,a2=0,s0=0,s1=0,s2=0;
        #pragma unroll
        for (int w = 0; w < 8; w++){
            a0 += sMij[w*6+0]; a1 += sMij[w*6+1]; a2 += sMij[w*6+2];
            s0 += sMij[w*6+3]; s1 += sMij[w*6+4]; s2 += sMij[w*6+5];
        }
        g_x[(b*NN+i)*3+0] += a0 + bp2v*s0;
        g_x[(b*NN+i)*3+1] += a1 + bp2v*s1;
        g_x[(b*NN+i)*3+2] += a2 + bp2v*s2;
    }
}

// ---------------- node update (Wm2 hoisted) + GRU ----------------
__global__ void k_node(const float* __restrict__ Wm2l, const float* __restrict__ bm2l,
                       const float* __restrict__ Wihl, const float* __restrict__ Whhl,
                       const float* __restrict__ bihl, const float* __restrict__ bhhl,
                       const float* __restrict__ mask){
    int i = blockIdx.x, b = blockIdx.y, tid = threadIdx.x;
    __shared__ float sS[DD], sh[DD], smn[DD];
    int idx = (b*NN+i)*DD + tid;
    sS[tid] = g_S[idx];
    sh[tid] = g_h[idx];
    __syncthreads();
    float mn = (float)NN * bm2l[tid];
    #pragma unroll 8
    for (int k = 0; k < DD; k++) mn += sS[k]*Wm2l[k*DD + tid];
    smn[tid] = mn;
    __syncthreads();
    float gir=bihl[tid], giz=bihl[DD+tid], gin=bihl[2*DD+tid];
    float ghr=bhhl[tid], ghz=bhhl[DD+tid], ghn=bhhl[2*DD+tid];
    #pragma unroll 4
    for (int k = 0; k < DD; k++){
        float mk = smn[k], hk = sh[k];
        gir += mk*Wihl[k*3*DD + tid];
        giz += mk*Wihl[k*3*DD + DD + tid];
        gin += mk*Wihl[k*3*DD + 2*DD + tid];
        ghr += hk*Whhl[k*3*DD + tid];
        ghz += hk*Whhl[k*3*DD + DD + tid];
        ghn += hk*Whhl[k*3*DD + 2*DD + tid];
    }
    float r = sigm_f(gir + ghr);
    float z = sigm_f(giz + ghz);
    float n = tanhf(gin + r*ghn);
    float hn = (1.f - z)*n + z*sh[tid];
    g_h[idx] = hn * mask[b*NN + i];
}

// ---------------- pool + head ----------------
__global__ void k_pool(const float* __restrict__ mask,
                       const float* __restrict__ Wc1, const float* __restrict__ bc1,
                       const float* __restrict__ Wc2, const float* __restrict__ bc2,
                       const float* __restrict__ Wc3, const float* __restrict__ bc3,
                       float* __restrict__ out){
    int b = blockIdx.x, tid = threadIdx.x;
    __shared__ float feat[DD], o1[DD], o2[64];
    float s = 0.f, ms = 0.f;
    for (int i = 0; i < NN; i++){
        float mk = mask[b*NN + i];
        s  += g_h[(b*NN+i)*DD + tid]*mk;
        ms += mk;
    }
    feat[tid] = s / fmaxf(ms, 1.f);
    __syncthreads();
    float t = bc1[tid];
    #pragma unroll 8
    for (int k = 0; k < DD; k++) t += feat[k]*Wc1[k*DD + tid];
    o1[tid] = silu_f(t);
    __syncthreads();
    if (tid < 64){
        float t2 = bc2[tid];
        #pragma unroll 8
        for (int k = 0; k < DD; k++) t2 += o1[k]*Wc2[k*64 + tid];
        o2[tid] = silu_f(t2);
    }
    __syncthreads();
    if (tid < 6){
        float t3 = bc3[tid];
        #pragma unroll
        for (int k = 0; k < 64; k++) t3 += o2[k]*Wc3[k*6 + tid];
        float r;
        if (tid < 3){
            r = (t3 > 20.f) ? t3 : log1pf(expf(t3));
        } else {
            r = (1.f / (1.f + expf(-t3))) * 180.f;
        }
        out[b*6 + tid] = r;
    }
}

extern "C" void kernel_launch(void* const* d_in, const int* in_sizes, int n_in,
                              void* d_out, int out_size){
    const float* pos   = (const float*)d_in[0];
    const float* oneh  = (const float*)d_in[1];
    const float* mask  = (const float*)d_in[2];
    const float* cell  = (const float*)d_in[3];
    const float* W_in1 = (const float*)d_in[4];
    const float* b_in1 = (const float*)d_in[5];
    const float* W_in2 = (const float*)d_in[6];
    const float* b_in2 = (const float*)d_in[7];
    const float* We1   = (const float*)d_in[8];
    const float* be1   = (const float*)d_in[9];
    const float* We2   = (const float*)d_in[10];
    const float* be2   = (const float*)d_in[11];
    const float* We3   = (const float*)d_in[12];
    const float* be3   = (const float*)d_in[13];
    const float* Wm1   = (const float*)d_in[14];
    const float* bm1   = (const float*)d_in[15];
    const float* Wm2   = (const float*)d_in[16];
    const float* bm2   = (const float*)d_in[17];
    const float* Wp1   = (const float*)d_in[18];
    const float* bp1   = (const float*)d_in[19];
    const float* Wp2   = (const float*)d_in[20];
    const float* bp2   = (const float*)d_in[21];
    const float* W_ih  = (const float*)d_in[22];
    const float* W_hh  = (const float*)d_in[23];
    const float* b_ih  = (const float*)d_in[24];
    const float* b_hh  = (const float*)d_in[25];
    const float* Wc1   = (const float*)d_in[26];
    const float* bc1   = (const float*)d_in[27];
    const float* Wc2   = (const float*)d_in[28];
    const float* bc2   = (const float*)d_in[29];
    const float* Wc3   = (const float*)d_in[30];
    const float* bc3   = (const float*)d_in[31];
    float* out = (float*)d_out;

    cudaFuncSetAttribute(k_edge, cudaFuncAttributeMaxDynamicSharedMemorySize, SMEMB);

    dim3 gBN(NN, BB);

    k_inv<<<1, 32>>>(cell);
    k_init<<<(BB*NN*3 + 127)/128, 128>>>(pos);
    k_frac<<<(BB*NN + 127)/128, 128>>>();
    k_prepW<<<LL, 256>>>(We2);
    k_embed<<<gBN, 128>>>(pos, oneh, W_in1, b_in1, W_in2, b_in2);

    for (int l = 0; l < LL; l++){
        k_A<<<gBN, 128>>>(We1 + l*257*DD);
        k_edge<<<gBN, 256, SMEMB>>>(We1 + l*257*DD, be1 + l*DD,
                                    be2 + l*DD, We3 + l*DD, be3 + l,
                                    Wm1 + l*DD, bm1 + l*DD,
                                    Wp1 + l*DD, bp1 + l*DD,
                                    Wp2 + l*DD, bp2 + l,
                                    cell, mask, l);
        k_node<<<gBN, 128>>>(Wm2 + l*DD*DD, bm2 + l*DD,
                             W_ih + l*DD*3*DD, W_hh + l*DD*3*DD,
                             b_ih + l*3*DD,    b_hh + l*3*DD, mask);
        k_frac<<<(BB*NN + 127)/128, 128>>>();
    }

    k_pool<<<BB, 128>>>(mask, Wc1, bc1, Wc2, bc2, Wc3, bc3, out);
}

// round 5
// speedup vs baseline: 5.8878x; 1.4131x over previous
#include <cuda_runtime.h>
#include <cuda_bf16.h>
#include <math.h>
#include <stdint.h>

#define BB 2
#define NN 320
#define DD 128
#define LL 4
#define OHH 100
#define KS 136   // smem row stride in bf16 elems (272 bytes)

// ---------------- device scratch (no allocs allowed) ----------------
__device__ float g_h[BB*NN*DD];
__device__ float g_x[BB*NN*3];
__device__ float g_A[BB*NN*DD];
__device__ float g_Bv[BB*NN*DD];
__device__ float g_invC[BB*9];
__device__ unsigned short g_We2bf[LL*DD*DD];   // per-layer B[n][k] = We2[k][n] in bf16

// ---------------- math helpers ----------------
__device__ __forceinline__ float tanh_ap(float x){
    float t; asm("tanh.approx.f32 %0, %1;" : "=f"(t) : "f"(x)); return t;
}
__device__ __forceinline__ float silu_f(float x){
    return 0.5f*x*(1.f + tanh_ap(0.5f*x));
}
__device__ __forceinline__ float sigm_f(float x){
    return 0.5f*(1.f + tanh_ap(0.5f*x));
}

__device__ __forceinline__ uint32_t smem_u32(const void* p){
    uint32_t a;
    asm("{ .reg .u64 t; cvta.to.shared.u64 t, %1; cvt.u32.u64 %0, t; }" : "=r"(a) : "l"(p));
    return a;
}
__device__ __forceinline__ void ldsm4(uint32_t& r0, uint32_t& r1, uint32_t& r2, uint32_t& r3, uint32_t a){
    asm volatile("ldmatrix.sync.aligned.m8n8.x4.shared.b16 {%0,%1,%2,%3}, [%4];"
                 : "=r"(r0),"=r"(r1),"=r"(r2),"=r"(r3) : "r"(a));
}
__device__ __forceinline__ void mma16816(float* c, uint32_t a0,uint32_t a1,uint32_t a2,uint32_t a3,
                                         uint32_t b0,uint32_t b1){
    asm volatile("mma.sync.aligned.m16n8k16.row.col.f32.bf16.bf16.f32 "
        "{%0,%1,%2,%3}, {%4,%5,%6,%7}, {%8,%9}, {%0,%1,%2,%3};"
        : "+f"(c[0]),"+f"(c[1]),"+f"(c[2]),"+f"(c[3])
        : "r"(a0),"r"(a1),"r"(a2),"r"(a3),"r"(b0),"r"(b1));
}

// ---------------- small kernels ----------------
__global__ void k_inv(const float* __restrict__ cell){
    int b = threadIdx.x;
    if (b >= BB) return;
    const float* c = cell + b*9;
    float a00=c[0],a01=c[1],a02=c[2];
    float a10=c[3],a11=c[4],a12=c[5];
    float a20=c[6],a21=c[7],a22=c[8];
    float C00 =  a11*a22 - a12*a21;
    float C01 = -(a10*a22 - a12*a20);
    float C02 =  a10*a21 - a11*a20;
    float C10 = -(a01*a22 - a02*a21);
    float C11 =  a00*a22 - a02*a20;
    float C12 = -(a00*a21 - a01*a20);
    float C20 =  a01*a12 - a02*a11;
    float C21 = -(a00*a12 - a02*a10);
    float C22 =  a00*a11 - a01*a10;
    float det = a00*C00 + a01*C01 + a02*C02;
    float id = 1.f/det;
    float* o = g_invC + b*9;
    o[0]=C00*id; o[1]=C10*id; o[2]=C20*id;
    o[3]=C01*id; o[4]=C11*id; o[5]=C21*id;
    o[6]=C02*id; o[7]=C12*id; o[8]=C22*id;
}

__global__ void k_init(const float* __restrict__ pos){
    int t = blockIdx.x*blockDim.x + threadIdx.x;
    if (t < BB*NN*3) g_x[t] = pos[t];
}

// prepare We2^T bf16: B[n][k] = We2[k][n]
__global__ void k_prepW(const float* __restrict__ We2){
    int l = blockIdx.x, tid = threadIdx.x;
    const float* W = We2 + l*DD*DD;
    unsigned short* dst = g_We2bf + l*DD*DD;
    for (int e = tid; e < DD*DD; e += 256){
        int n = e >> 7, k = e & 127;
        dst[e] = __bfloat16_as_ushort(__float2bfloat16_rn(W[k*DD + n]));
    }
}

__global__ void k_embed(const float* __restrict__ pos, const float* __restrict__ oneh,
                        const float* __restrict__ W1, const float* __restrict__ b1,
                        const float* __restrict__ W2, const float* __restrict__ b2){
    int i = blockIdx.x, b = blockIdx.y, tid = threadIdx.x;
    __shared__ float sin_[OHH+3];
    __shared__ float sh1[DD];
    if (tid < OHH+3){
        sin_[tid] = (tid < 3) ? pos[(b*NN+i)*3 + tid] : oneh[(b*NN+i)*OHH + (tid-3)];
    }
    __syncthreads();
    float t = b1[tid];
    #pragma unroll 8
    for (int k = 0; k < OHH+3; k++) t += sin_[k]*W1[k*DD + tid];
    sh1[tid] = silu_f(t);
    __syncthreads();
    float t2 = b2[tid];
    #pragma unroll 8
    for (int k = 0; k < DD; k++) t2 += sh1[k]*W2[k*DD + tid];
    g_h[(b*NN+i)*DD + tid] = t2;
}

__global__ void k_A(const float* __restrict__ We1l){
    int i = blockIdx.x, b = blockIdx.y, tid = threadIdx.x;
    __shared__ float sh[DD];
    sh[tid] = g_h[(b*NN+i)*DD + tid];
    __syncthreads();
    float a = 0.f, bv = 0.f;
    #pragma unroll 8
    for (int k = 0; k < DD; k++){
        float hv = sh[k];
        a  += hv * We1l[k*DD + tid];
        bv += hv * We1l[(DD+k)*DD + tid];
    }
    g_A[(b*NN+i)*DD + tid]  = a;
    g_Bv[(b*NN+i)*DD + tid] = bv;
}

// ---------------- fused heavy kernel: edge GEMM + messages + GRU per (b,i) ----------------
// dynamic smem byte offsets:
#define OFF_B    0                       // bf16 [128][KS]  = 34816 B
#define OFF_M1   34816                   // bf16 [64][KS]   = 17408 B
#define OFF_GEO  52224                   // 5 x 320 floats  = 6400 B
#define OFF_WT   58624                   // 1280 floats     = 5120 B
#define OFF_MIJ  63744                   // 320 floats      = 1280 B
#define OFF_PART 65024                   // 128 floats      = 512 B
#define OFF_SS   65536                   // 128 floats
#define OFF_SMN  66048                   // 128 floats
#define OFF_SH   66560                   // 128 floats
#define OFF_RED  67072                   // 32 floats
#define SMEMB    67200

__global__ void __launch_bounds__(256, 3) k_edge(
    const float* __restrict__ We1l, const float* __restrict__ be1l,
    const float* __restrict__ be2l, const float* __restrict__ We3l,
    const float* __restrict__ be3l,
    const float* __restrict__ Wm1l, const float* __restrict__ bm1l,
    const float* __restrict__ Wp1l, const float* __restrict__ bp1l,
    const float* __restrict__ Wp2l, const float* __restrict__ bp2l,
    const float* __restrict__ Wm2l, const float* __restrict__ bm2l,
    const float* __restrict__ Wihl, const float* __restrict__ Whhl,
    const float* __restrict__ bihl, const float* __restrict__ bhhl,
    const float* __restrict__ cell, const float* __restrict__ mask, int layer)
{
    extern __shared__ char base[];
    __nv_bfloat16* sB  = (__nv_bfloat16*)(base + OFF_B);
    __nv_bfloat16* sM1 = (__nv_bfloat16*)(base + OFF_M1);
    float* sDij = (float*)(base + OFF_GEO);
    float* sRx  = sDij + 320;
    float* sRy  = sRx + 320;
    float* sRz  = sRy + 320;
    float* sPm  = sRz + 320;
    float* sWt  = (float*)(base + OFF_WT);
    float* sMij = (float*)(base + OFF_MIJ);
    float* sPart= (float*)(base + OFF_PART);
    float* sS   = (float*)(base + OFF_SS);
    float* smn  = (float*)(base + OFF_SMN);
    float* sh   = (float*)(base + OFF_SH);
    float* sRed = (float*)(base + OFF_RED);

    int i = blockIdx.x, b = blockIdx.y;
    int tid = threadIdx.x, wid = tid >> 5, lane = tid & 31;

    // stage B[n][k] bf16 into padded smem
    {
        const uint4* src = (const uint4*)(g_We2bf + layer*DD*DD);
        #pragma unroll
        for (int q = 0; q < 8; q++){
            int e = tid + q*256;
            int n = e >> 4, k0 = (e & 15) << 3;
            *(uint4*)(sB + n*KS + k0) = src[e];
        }
    }
    if (tid < 128){
        sWt[tid]       = be2l[tid];
        sWt[128+tid]   = We3l[tid];
        sWt[256+tid]   = Wm1l[tid];
        sWt[384+tid]   = bm1l[tid];
        ((float4*)(sWt+512))[tid] = make_float4(Wp1l[tid], bp1l[tid], Wp2l[tid], 0.f);
        sWt[1024+tid]  = g_A[(b*NN+i)*DD + tid] + be1l[tid];   // tb
        sWt[1152+tid]  = We1l[256*DD + tid];                    // wd
        sh[tid]        = g_h[(b*NN+i)*DD + tid];                // old h row
    }
    float mi = mask[b*NN + i];
    // geometry for all 320 j, frac computed inline from g_x
    {
        const float* ic = g_invC + b*9;
        float i0=ic[0],i1=ic[1],i2=ic[2],i3=ic[3],i4=ic[4],i5=ic[5],i6=ic[6],i7=ic[7],i8=ic[8];
        float xi0=g_x[(b*NN+i)*3+0], xi1=g_x[(b*NN+i)*3+1], xi2=g_x[(b*NN+i)*3+2];
        float fi0 = xi0*i0 + xi1*i3 + xi2*i6;
        float fi1 = xi0*i1 + xi1*i4 + xi2*i7;
        float fi2 = xi0*i2 + xi1*i5 + xi2*i8;
        float c0=cell[b*9+0],c1=cell[b*9+1],c2=cell[b*9+2];
        float c3=cell[b*9+3],c4=cell[b*9+4],c5=cell[b*9+5];
        float c6=cell[b*9+6],c7=cell[b*9+7],c8=cell[b*9+8];
        for (int j = tid; j < NN; j += 256){
            float xj0=g_x[(b*NN+j)*3+0], xj1=g_x[(b*NN+j)*3+1], xj2=g_x[(b*NN+j)*3+2];
            float f0 = xj0*i0 + xj1*i3 + xj2*i6 - fi0;
            float f1 = xj0*i1 + xj1*i4 + xj2*i7 - fi1;
            float f2 = xj0*i2 + xj1*i5 + xj2*i8 - fi2;
            f0 -= rintf(f0); f1 -= rintf(f1); f2 -= rintf(f2);
            float rx = f0*c0 + f1*c3 + f2*c6;
            float ry = f0*c1 + f1*c4 + f2*c7;
            float rz = f0*c2 + f1*c5 + f2*c8;
            float dij = sqrtf(rx*rx + ry*ry + rz*rz + 1e-12f);
            float pm = mi * mask[b*NN + j];
            sDij[j] = dij*pm + (1.f - pm)*1e6f;
            sRx[j] = rx*pm; sRy[j] = ry*pm; sRz[j] = rz*pm;
            sPm[j] = pm;
        }
    }
    __syncthreads();

    float be3v = be3l[0], bp2v = bp2l[0];

    // warp tiling: 4 M-chunks of 16 rows, 2 N-chunks of 64 cols
    int wm = (wid & 3) * 16;
    int wn = (wid >> 2) * 64;

    uint32_t sM1a = smem_u32(sM1);
    uint32_t sBa  = smem_u32(sB);
    int lr = lane & 7;
    int lb3 = (lane >> 3) & 1;
    int lb4 = lane >> 4;
    uint32_t aBase = sM1a + (uint32_t)(((wm + (lane & 15))*KS + lb4*8) * 2);
    uint32_t bBase[4];
    #pragma unroll
    for (int ntp = 0; ntp < 4; ntp++)
        bBase[ntp] = sBa + (uint32_t)(((wn + (ntp*2 + lb4)*8 + lr)*KS + lb3*8) * 2);

    for (int T = 0; T < 5; T++){
        // ---- m1: 64 rows x 128 k bf16; 4 threads per row ----
        {
            int row = tid >> 2;
            int k0 = (tid & 3) * 32;
            int jg = T*64 + row;
            float dij = sDij[jg];
            const float4* bv = (const float4*)(g_Bv + (size_t)(b*NN + jg)*DD + k0);
            const float4* tb = (const float4*)(sWt + 1024 + k0);
            const float4* wd = (const float4*)(sWt + 1152 + k0);
            __nv_bfloat16* row_p = sM1 + row*KS + k0;
            #pragma unroll
            for (int u = 0; u < 4; u++){
                float4 bva = bv[2*u],   bvb = bv[2*u+1];
                float4 tba = tb[2*u],   tbb = tb[2*u+1];
                float4 wda = wd[2*u],   wdb = wd[2*u+1];
                float v0 = silu_f(tba.x + bva.x + dij*wda.x);
                float v1 = silu_f(tba.y + bva.y + dij*wda.y);
                float v2 = silu_f(tba.z + bva.z + dij*wda.z);
                float v3 = silu_f(tba.w + bva.w + dij*wda.w);
                float v4 = silu_f(tbb.x + bvb.x + dij*wdb.x);
                float v5 = silu_f(tbb.y + bvb.y + dij*wdb.y);
                float v6 = silu_f(tbb.z + bvb.z + dij*wdb.z);
                float v7 = silu_f(tbb.w + bvb.w + dij*wdb.w);
                uint4 pk;
                pk.x = (uint32_t)__bfloat16_as_ushort(__float2bfloat16_rn(v0))
                     | ((uint32_t)__bfloat16_as_ushort(__float2bfloat16_rn(v1)) << 16);
                pk.y = (uint32_t)__bfloat16_as_ushort(__float2bfloat16_rn(v2))
                     | ((uint32_t)__bfloat16_as_ushort(__float2bfloat16_rn(v3)) << 16);
                pk.z = (uint32_t)__bfloat16_as_ushort(__float2bfloat16_rn(v4))
                     | ((uint32_t)__bfloat16_as_ushort(__float2bfloat16_rn(v5)) << 16);
                pk.w = (uint32_t)__bfloat16_as_ushort(__float2bfloat16_rn(v6))
                     | ((uint32_t)__bfloat16_as_ushort(__float2bfloat16_rn(v7)) << 16);
                *(uint4*)(row_p + u*8) = pk;
            }
        }
        __syncthreads();

        // ---- GEMM: warp computes C[16 j][64 t] ----
        float acc[8][4];
        #pragma unroll
        for (int nt = 0; nt < 8; nt++)
            #pragma unroll
            for (int c = 0; c < 4; c++) acc[nt][c] = 0.f;

        uint32_t aA = aBase;
        uint32_t bA0 = bBase[0], bA1 = bBase[1], bA2 = bBase[2], bA3 = bBase[3];
        #pragma unroll
        for (int ks = 0; ks < 8; ks++){
            uint32_t a0,a1,a2,a3;
            ldsm4(a0,a1,a2,a3, aA);
            uint32_t b0,b1,b2,b3;
            ldsm4(b0,b1,b2,b3, bA0);
            mma16816(acc[0], a0,a1,a2,a3, b0,b1);
            mma16816(acc[1], a0,a1,a2,a3, b2,b3);
            ldsm4(b0,b1,b2,b3, bA1);
            mma16816(acc[2], a0,a1,a2,a3, b0,b1);
            mma16816(acc[3], a0,a1,a2,a3, b2,b3);
            ldsm4(b0,b1,b2,b3, bA2);
            mma16816(acc[4], a0,a1,a2,a3, b0,b1);
            mma16816(acc[5], a0,a1,a2,a3, b2,b3);
            ldsm4(b0,b1,b2,b3, bA3);
            mma16816(acc[6], a0,a1,a2,a3, b0,b1);
            mma16816(acc[7], a0,a1,a2,a3, b2,b3);
            aA += 32; bA0 += 32; bA1 += 32; bA2 += 32; bA3 += 32;
        }

        // ---- epilogue: m2 = silu(C + be2), dot with we3 per j ----
        {
            int colq = wn + (lane & 3)*2;
            float d0 = 0.f, d1 = 0.f;
            #pragma unroll
            for (int nt = 0; nt < 8; nt++){
                int col = colq + nt*8;
                float w0 = sWt[128+col], w1 = sWt[128+col+1];
                float e0 = sWt[col], e1 = sWt[col+1];
                d0 += silu_f(acc[nt][0] + e0)*w0 + silu_f(acc[nt][1] + e1)*w1;
                d1 += silu_f(acc[nt][2] + e0)*w0 + silu_f(acc[nt][3] + e1)*w1;
            }
            d0 += __shfl_xor_sync(0xffffffffu, d0, 1);
            d0 += __shfl_xor_sync(0xffffffffu, d0, 2);
            d1 += __shfl_xor_sync(0xffffffffu, d1, 1);
            d1 += __shfl_xor_sync(0xffffffffu, d1, 2);
            if ((lane & 3) == 0){
                int row = wm + (lane >> 2);
                sPart[(wid >> 2)*64 + row]     = d0;
                sPart[(wid >> 2)*64 + row + 8] = d1;
            }
        }
        __syncthreads();
        if (tid < 64){
            int j = T*64 + tid;
            sMij[j] = (sPart[tid] + sPart[64+tid] + be3v) * sPm[j];
        }
        __syncthreads();
    }

    // -------- fused final epilogue: warp-split GRU vs phi --------
    if (wid < 4){
        int t = tid;   // 0..127
        // S[t] = sum_j silu(mij*wm1[t]+bm1[t])
        float wm1 = sWt[256+t], bm1v = sWt[384+t];
        float s = 0.f;
        #pragma unroll 4
        for (int j = 0; j < NN; j++)
            s += silu_f(fmaf(sMij[j], wm1, bm1v));
        sS[t] = s;
        asm volatile("bar.sync 1, 128;" ::: "memory");
        // m_node = S @ Wm2 + NN*bm2
        float mn = (float)NN * bm2l[t];
        #pragma unroll 4
        for (int k = 0; k < DD; k++) mn += sS[k]*Wm2l[k*DD + t];
        smn[t] = mn;
        asm volatile("bar.sync 1, 128;" ::: "memory");
        // GRU gates
        float gir=bihl[t], giz=bihl[DD+t], gin=bihl[2*DD+t];
        float ghr=bhhl[t], ghz=bhhl[DD+t], ghn=bhhl[2*DD+t];
        #pragma unroll 4
        for (int k = 0; k < DD; k++){
            float mk = smn[k], hk = sh[k];
            gir += mk*Wihl[k*3*DD + t];
            giz += mk*Wihl[k*3*DD + DD + t];
            gin += mk*Wihl[k*3*DD + 2*DD + t];
            ghr += hk*Whhl[k*3*DD + t];
            ghz += hk*Whhl[k*3*DD + DD + t];
            ghn += hk*Whhl[k*3*DD + 2*DD + t];
        }
        float r = sigm_f(gir + ghr);
        float z = sigm_f(giz + ghz);
        float n = tanh_ap(gin + r*ghn);
        g_h[(b*NN+i)*DD + t] = ((1.f - z)*n + z*sh[t]) * mi;
    } else {
        // phi: threads 128..255, j in {p, p+128, p+256<320}
        int p = tid - 128;
        const float4* phi4 = (const float4*)(sWt + 512);
        float dx0=0.f,dx1=0.f,dx2=0.f, sr0=0.f,sr1=0.f,sr2=0.f;
        #pragma unroll
        for (int rep = 0; rep < 3; rep++){
            int j = p + rep*128;
            if (j < NN){
                float mij = sMij[j];
                float inner = 0.f;
                #pragma unroll 4
                for (int t2 = 0; t2 < DD; t2++){
                    float4 w = phi4[t2];
                    inner += silu_f(fmaf(mij, w.x, w.y)) * w.z;
                }
                dx0 += sRx[j]*inner; dx1 += sRy[j]*inner; dx2 += sRz[j]*inner;
                sr0 += sRx[j]; sr1 += sRy[j]; sr2 += sRz[j];
            }
        }
        float v[6] = {dx0,dx1,dx2,sr0,sr1,sr2};
        #pragma unroll
        for (int c = 0; c < 6; c++)
            #pragma unroll
            for (int o = 16; o; o >>= 1) v[c] += __shfl_xor_sync(0xffffffffu, v[c], o);
        if (lane == 0){
            #pragma unroll
            for (int c = 0; c < 6; c++) sRed[(wid-4)*6 + c] = v[c];
        }
    }
    __syncthreads();
    if (tid == 0){
        float a0=0,a1=0,a2=0,s0=0,s1=0,s2=0;
        #pragma unroll
        for (int w = 0; w < 4; w++){
            a0 += sRed[w*6+0]; a1 += sRed[w*6+1]; a2 += sRed[w*6+2];
            s0 += sRed[w*6+3]; s1 += sRed[w*6+4]; s2 += sRed[w*6+5];
        }
        g_x[(b*NN+i)*3+0] += a0 + bp2v*s0;
        g_x[(b*NN+i)*3+1] += a1 + bp2v*s1;
        g_x[(b*NN+i)*3+2] += a2 + bp2v*s2;
    }
}

// ---------------- pool + head ----------------
__global__ void k_pool(const float* __restrict__ mask,
                       const float* __restrict__ Wc1, const float* __restrict__ bc1,
                       const float* __restrict__ Wc2, const float* __restrict__ bc2,
                       const float* __restrict__ Wc3, const float* __restrict__ bc3,
                       float* __restrict__ out){
    int b = blockIdx.x, tid = threadIdx.x;
    __shared__ float feat[DD], o1[DD], o2[64];
    float s = 0.f, ms = 0.f;
    for (int i = 0; i < NN; i++){
        float mk = mask[b*NN + i];
        s  += g_h[(b*NN+i)*DD + tid]*mk;
        ms += mk;
    }
    feat[tid] = s / fmaxf(ms, 1.f);
    __syncthreads();
    float t = bc1[tid];
    #pragma unroll 8
    for (int k = 0; k < DD; k++) t += feat[k]*Wc1[k*DD + tid];
    o1[tid] = silu_f(t);
    __syncthreads();
    if (tid < 64){
        float t2 = bc2[tid];
        #pragma unroll 8
        for (int k = 0; k < DD; k++) t2 += o1[k]*Wc2[k*64 + tid];
        o2[tid] = silu_f(t2);
    }
    __syncthreads();
    if (tid < 6){
        float t3 = bc3[tid];
        #pragma unroll
        for (int k = 0; k < 64; k++) t3 += o2[k]*Wc3[k*6 + tid];
        float r;
        if (tid < 3){
            r = (t3 > 20.f) ? t3 : log1pf(expf(t3));
        } else {
            r = (1.f / (1.f + expf(-t3))) * 180.f;
        }
        out[b*6 + tid] = r;
    }
}

extern "C" void kernel_launch(void* const* d_in, const int* in_sizes, int n_in,
                              void* d_out, int out_size){
    const float* pos   = (const float*)d_in[0];
    const float* oneh  = (const float*)d_in[1];
    const float* mask  = (const float*)d_in[2];
    const float* cell  = (const float*)d_in[3];
    const float* W_in1 = (const float*)d_in[4];
    const float* b_in1 = (const float*)d_in[5];
    const float* W_in2 = (const float*)d_in[6];
    const float* b_in2 = (const float*)d_in[7];
    const float* We1   = (const float*)d_in[8];
    const float* be1   = (const float*)d_in[9];
    const float* We2   = (const float*)d_in[10];
    const float* be2   = (const float*)d_in[11];
    const float* We3   = (const float*)d_in[12];
    const float* be3   = (const float*)d_in[13];
    const float* Wm1   = (const float*)d_in[14];
    const float* bm1   = (const float*)d_in[15];
    const float* Wm2   = (const float*)d_in[16];
    const float* bm2   = (const float*)d_in[17];
    const float* Wp1   = (const float*)d_in[18];
    const float* bp1   = (const float*)d_in[19];
    const float* Wp2   = (const float*)d_in[20];
    const float* bp2   = (const float*)d_in[21];
    const float* W_ih  = (const float*)d_in[22];
    const float* W_hh  = (const float*)d_in[23];
    const float* b_ih  = (const float*)d_in[24];
    const float* b_hh  = (const float*)d_in[25];
    const float* Wc1   = (const float*)d_in[26];
    const float* bc1   = (const float*)d_in[27];
    const float* Wc2   = (const float*)d_in[28];
    const float* bc2   = (const float*)d_in[29];
    const float* Wc3   = (const float*)d_in[30];
    const float* bc3   = (const float*)d_in[31];
    float* out = (float*)d_out;

    cudaFuncSetAttribute(k_edge, cudaFuncAttributeMaxDynamicSharedMemorySize, SMEMB);

    dim3 gBN(NN, BB);

    k_inv<<<1, 32>>>(cell);
    k_init<<<(BB*NN*3 + 127)/128, 128>>>(pos);
    k_prepW<<<LL, 256>>>(We2);
    k_embed<<<gBN, 128>>>(pos, oneh, W_in1, b_in1, W_in2, b_in2);

    for (int l = 0; l < LL; l++){
        k_A<<<gBN, 128>>>(We1 + l*257*DD);
        k_edge<<<gBN, 256, SMEMB>>>(We1 + l*257*DD, be1 + l*DD,
                                    be2 + l*DD, We3 + l*DD, be3 + l,
                                    Wm1 + l*DD, bm1 + l*DD,
                                    Wp1 + l*DD, bp1 + l*DD,
                                    Wp2 + l*DD, bp2 + l,
                                    Wm2 + l*DD*DD, bm2 + l*DD,
                                    W_ih + l*DD*3*DD, W_hh + l*DD*3*DD,
                                    b_ih + l*3*DD,    b_hh + l*3*DD,
                                    cell, mask, l);
    }

    k_pool<<<BB, 128>>>(mask, Wc1, bc1, Wc2, bc2, Wc3, bc3, out);
}